// round 8
// baseline (speedup 1.0000x reference)
#include <cuda_runtime.h>
#include <cuda_fp16.h>
#include <cstdint>
#include <math.h>

#define NB 16
#define NC 64
#define IMG 256
#define PLANE 65536

// scratch (device globals — no allocation allowed)
__device__ float g_y[NB * 64 * NC];                 // [b][n][c] pooled tokens
__device__ unsigned long long g_xpack[16777216];    // x fp16: [bc][ig][nh][k=64][px=128] (134MB)
__device__ __align__(16) unsigned char g_Apack[NB * 18432]; // dist fp16 hi(9216)+lo(9216), 144B rows

__device__ __forceinline__ uint32_t smem_u32(const void* p) {
    uint32_t a;
    asm("{ .reg .u64 t; cvta.to.shared.u64 t, %1; cvt.u32.u64 %0, t; }"
        : "=r"(a) : "l"(p));
    return a;
}

// ---------------------------------------------------------------------------
// Kernel A: adaptive avg pool 8x8 + fp16 windowed repack of x.
// One CTA per (b,c) plane. row = mr*32 + ig*8 + il; warp = il, pass = mr*4+ig.
// Repack (u64 units): g_xpack[bc*16384 + ig*4096 + nh*2048 + k*32
//                             + (il&3)*8 + jc/4],  nh = il>>2, k = mr*8+mc.
// Each (ig,nh) tile is 16KB contiguous for streaming cp.async in att.
// ---------------------------------------------------------------------------
__global__ __launch_bounds__(256) void pool_kernel(const float* __restrict__ x) {
    int bc = blockIdx.x;
    const float* plane = x + (size_t)bc * PLANE;
    int t = threadIdx.x;
    int warp = t >> 5, lane = t & 31;

    __shared__ float wsum[64];
    if (t < 64) wsum[t] = 0.f;
    __syncthreads();

    int mc1 = lane >> 3;               // window col for first float4 (0..3)
    int jq  = lane & 7;                // jc/4 within window
    int nh  = warp >> 2;
    int il4 = warp & 3;
    unsigned long long* xp = g_xpack + (size_t)bc * 16384 + nh * 2048 + il4 * 8 + jq;

    for (int pass = 0; pass < 32; pass++) {
        int row = pass * 8 + warp;
        int mr = pass >> 2, ig = pass & 3;
        const float4* rp = (const float4*)(plane + row * IMG);
        float4 v1 = rp[lane];
        float4 v2 = rp[lane + 32];

        // fp16 repack (half4 = one u64 per float4)
        {
            __half2 a0 = __floats2half2_rn(v1.x, v1.y);
            __half2 a1 = __floats2half2_rn(v1.z, v1.w);
            __half2 b0 = __floats2half2_rn(v2.x, v2.y);
            __half2 b1 = __floats2half2_rn(v2.z, v2.w);
            unsigned long long u1 = ((unsigned long long)*(uint32_t*)&a1 << 32) | *(uint32_t*)&a0;
            unsigned long long u2 = ((unsigned long long)*(uint32_t*)&b1 << 32) | *(uint32_t*)&b0;
            xp[ig * 4096 + (mr * 8 + mc1) * 32]       = u1;
            xp[ig * 4096 + (mr * 8 + mc1 + 4) * 32]   = u2;
        }

        float s1 = v1.x + v1.y + v1.z + v1.w;
        float s2 = v2.x + v2.y + v2.z + v2.w;
        s1 += __shfl_xor_sync(~0u, s1, 4);
        s1 += __shfl_xor_sync(~0u, s1, 2);
        s1 += __shfl_xor_sync(~0u, s1, 1);
        s2 += __shfl_xor_sync(~0u, s2, 4);
        s2 += __shfl_xor_sync(~0u, s2, 2);
        s2 += __shfl_xor_sync(~0u, s2, 1);
        if ((lane & 7) == 0) {
            int wr = row >> 5;
            atomicAdd(&wsum[wr * 8 + (lane >> 3)], s1);
            atomicAdd(&wsum[wr * 8 + (lane >> 3) + 4], s2);
        }
    }
    __syncthreads();
    if (t < 64) {
        int b = bc >> 6, c = bc & 63;
        g_y[((size_t)b * 64 + t) * NC + c] = wsum[t] * (1.0f / 1024.0f);
    }
}

// ---------------------------------------------------------------------------
// Kernel B: q = yWq^T, k = yWk^T, dist = softmax(q k^T / 8). One CTA per batch.
// Output: A packed fp16 hi/lo, 144B rows (the att smem image), to g_Apack.
// ---------------------------------------------------------------------------
__global__ __launch_bounds__(256) void dist_kernel(const float* __restrict__ Wq,
                                                   const float* __restrict__ Wk) {
    __shared__ float sY[4096];
    __shared__ float sA[4096];
    __shared__ float sB2[4096];
    int b = blockIdx.x, t = threadIdx.x;

    for (int idx = t; idx < 4096; idx += 256) {
        sY[idx]  = g_y[b * 4096 + idx];
        sA[idx]  = Wq[idx];
        sB2[idx] = Wk[idx];
    }
    __syncthreads();

    int n = t >> 2;
    int kk = (t & 3) * 16;

    float qv[16], kv[16];
    #pragma unroll
    for (int e = 0; e < 16; e++) {
        float aq = 0.f, ak = 0.f;
        const float* yr = &sY[n * 64];
        const float* wq = &sA[(kk + e) * 64];
        const float* wk = &sB2[(kk + e) * 64];
        #pragma unroll
        for (int c = 0; c < 64; c++) {
            aq = fmaf(yr[c], wq[c], aq);
            ak = fmaf(yr[c], wk[c], ak);
        }
        qv[e] = aq; kv[e] = ak;
    }
    __syncthreads();
    #pragma unroll
    for (int e = 0; e < 16; e++) {
        sA[n * 64 + kk + e]  = qv[e];
        sB2[n * 64 + kk + e] = kv[e];
    }
    __syncthreads();

    float sv[16];
    #pragma unroll
    for (int e = 0; e < 16; e++) {
        int m = kk + e;
        float s = 0.f;
        const float* qr = &sA[n * 64];
        const float* kr = &sB2[m * 64];
        #pragma unroll
        for (int k = 0; k < 64; k++) s = fmaf(qr[k], kr[k], s);
        sv[e] = s * 0.125f;
    }
    __syncthreads();
    #pragma unroll
    for (int e = 0; e < 16; e++) sY[n * 64 + kk + e] = sv[e];
    __syncthreads();

    // softmax + fp16 hi/lo pack: lane covers col pair (2*lane, 2*lane+1)
    int warp = t >> 5, lane = t & 31;
    unsigned char* ap = g_Apack + b * 18432;
    for (int j = 0; j < 8; j++) {
        int row = warp * 8 + j;
        float2 v = *(const float2*)&sY[row * 64 + 2 * lane];
        float mx = fmaxf(v.x, v.y);
        for (int d = 16; d >= 1; d >>= 1) mx = fmaxf(mx, __shfl_xor_sync(~0u, mx, d));
        float e0 = expf(v.x - mx), e1 = expf(v.y - mx);
        float s = e0 + e1;
        for (int d = 16; d >= 1; d >>= 1) s += __shfl_xor_sync(~0u, s, d);
        float inv = 1.0f / s;
        e0 *= inv; e1 *= inv;
        __half2 h = __floats2half2_rn(e0, e1);
        float2 hf = __half22float2(h);
        __half2 l = __floats2half2_rn(e0 - hf.x, e1 - hf.y);
        *(uint32_t*)(ap + row * 144 + lane * 4)        = *(uint32_t*)&h;
        *(uint32_t*)(ap + 9216 + row * 144 + lane * 4) = *(uint32_t*)&l;
    }
}

// ---------------------------------------------------------------------------
// Kernel C (att): persistent-(b,c) streaming fp16 GEMM with B double-buffer.
// 1024 CTAs; each runs 8 tiles (ig,nh). A loaded once (cp.async), B tile i+1
// prefetched while tile i computes. Per tile: ldmatrix + 64 HMMA/warp + scatter.
// ---------------------------------------------------------------------------
#define SM_A  0            // 18432 B (hi 9216 + lo 9216), 144B rows
#define SM_B0 18432        // 64 rows * 272B = 17408
#define SM_B1 35840
#define SMEM_ATT 53248

__global__ void __launch_bounds__(256, 3) att_kernel(float* __restrict__ out) {
    extern __shared__ char sm[];
    uint32_t sbase = smem_u32(sm);
    int t = threadIdx.x;
    int wid = t >> 5, lane = t & 31;
    int wm = wid >> 2, wn = wid & 3;

    int blk = blockIdx.x;
    int c = blk & 63;
    int b = blk >> 6;

    const char* gB = (const char*)g_xpack + (size_t)blk * 131072;

    // ---- group 0: A image + B tile 0 ----
    {
        const char* gA = (const char*)g_Apack + b * 18432;
        #pragma unroll
        for (int idx = t; idx < 1152; idx += 256) {
            uint32_t d = sbase + SM_A + idx * 16;
            asm volatile("cp.async.cg.shared.global [%0], [%1], 16;"
                         :: "r"(d), "l"(gA + idx * 16));
        }
        #pragma unroll
        for (int idx = t; idx < 1024; idx += 256) {
            int row = idx >> 4, ch = idx & 15;
            uint32_t d = sbase + SM_B0 + row * 272 + ch * 16;
            asm volatile("cp.async.cg.shared.global [%0], [%1], 16;"
                         :: "r"(d), "l"(gB + row * 256 + ch * 16));
        }
        asm volatile("cp.async.commit_group;");
    }

    int row16 = lane & 15;
    uint32_t aH = sbase + SM_A + (uint32_t)(wm * 32 + row16) * 144u + (uint32_t)(lane >> 4) * 16u;
    uint32_t aL = aH + 9216u;
    uint32_t bLane = (uint32_t)row16 * 272u + (uint32_t)(wn * 64);
    float* oplane = out + (size_t)blk * PLANE;

    uint32_t bufOff[2] = { sbase + SM_B0, sbase + SM_B1 };

    for (int i = 0; i < 8; i++) {
        __syncthreads();   // everyone done reading buf (i+1)&1 from tile i-1
        if (i < 7) {
            const char* src = gB + (size_t)(i + 1) * 16384;
            uint32_t dst = bufOff[(i + 1) & 1];
            #pragma unroll
            for (int idx = t; idx < 1024; idx += 256) {
                int row = idx >> 4, ch = idx & 15;
                asm volatile("cp.async.cg.shared.global [%0], [%1], 16;"
                             :: "r"(dst + row * 272 + ch * 16), "l"(src + row * 256 + ch * 16));
            }
            asm volatile("cp.async.commit_group;");
            asm volatile("cp.async.wait_group 1;" ::: "memory");
        } else {
            asm volatile("cp.async.wait_group 0;" ::: "memory");
        }
        __syncthreads();   // tile i data visible to all

        // ---- MMA on buf i&1 ----
        float acc[2][4][4];
        #pragma unroll
        for (int mt = 0; mt < 2; mt++)
            #pragma unroll
            for (int nt = 0; nt < 4; nt++) {
                acc[mt][nt][0] = 0.f; acc[mt][nt][1] = 0.f;
                acc[mt][nt][2] = 0.f; acc[mt][nt][3] = 0.f;
            }
        uint32_t bB = bufOff[i & 1] + bLane;

        #pragma unroll
        for (int kk = 0; kk < 4; kk++) {
            uint32_t bh[4][2];
            #pragma unroll
            for (int nt = 0; nt < 4; nt++) {
                uint32_t addr = bB + (uint32_t)(kk * 16) * 272u + (uint32_t)(nt * 16);
                asm volatile("ldmatrix.sync.aligned.m8n8.x2.trans.shared.b16 {%0,%1}, [%2];"
                             : "=r"(bh[nt][0]), "=r"(bh[nt][1]) : "r"(addr));
            }
            #pragma unroll
            for (int mt = 0; mt < 2; mt++) {
                uint32_t af[4];
                uint32_t addr = aH + (uint32_t)(mt * 16) * 144u + (uint32_t)(kk * 32);
                asm volatile("ldmatrix.sync.aligned.m8n8.x4.shared.b16 {%0,%1,%2,%3}, [%4];"
                             : "=r"(af[0]), "=r"(af[1]), "=r"(af[2]), "=r"(af[3]) : "r"(addr));
                #pragma unroll
                for (int nt = 0; nt < 4; nt++)
                    asm volatile(
                        "mma.sync.aligned.m16n8k16.row.col.f32.f16.f16.f32 "
                        "{%0,%1,%2,%3}, {%4,%5,%6,%7}, {%8,%9}, {%0,%1,%2,%3};"
                        : "+f"(acc[mt][nt][0]), "+f"(acc[mt][nt][1]),
                          "+f"(acc[mt][nt][2]), "+f"(acc[mt][nt][3])
                        : "r"(af[0]), "r"(af[1]), "r"(af[2]), "r"(af[3]),
                          "r"(bh[nt][0]), "r"(bh[nt][1]));
            }
            #pragma unroll
            for (int mt = 0; mt < 2; mt++) {
                uint32_t af[4];
                uint32_t addr = aL + (uint32_t)(mt * 16) * 144u + (uint32_t)(kk * 32);
                asm volatile("ldmatrix.sync.aligned.m8n8.x4.shared.b16 {%0,%1,%2,%3}, [%4];"
                             : "=r"(af[0]), "=r"(af[1]), "=r"(af[2]), "=r"(af[3]) : "r"(addr));
                #pragma unroll
                for (int nt = 0; nt < 4; nt++)
                    asm volatile(
                        "mma.sync.aligned.m16n8k16.row.col.f32.f16.f16.f32 "
                        "{%0,%1,%2,%3}, {%4,%5,%6,%7}, {%8,%9}, {%0,%1,%2,%3};"
                        : "+f"(acc[mt][nt][0]), "+f"(acc[mt][nt][1]),
                          "+f"(acc[mt][nt][2]), "+f"(acc[mt][nt][3])
                        : "r"(af[0]), "r"(af[1]), "r"(af[2]), "r"(af[3]),
                          "r"(bh[nt][0]), "r"(bh[nt][1]));
            }
        }

        // ---- epilogue: direct scatter (fully-used 32B sectors) ----
        {
            int ig = i >> 1, nh = i & 1;
            int g = lane >> 2, tig = lane & 3;
            int rowbase = ig * 8 + nh * 4 + wn;     // il = nh*4 + wn
            #pragma unroll
            for (int mt = 0; mt < 2; mt++) {
                #pragma unroll
                for (int nt = 0; nt < 4; nt++) {
                    int jc = nt * 8 + tig * 2;
                    int n1 = wm * 32 + mt * 16 + g;
                    int n2 = n1 + 8;
                    float* p1 = oplane + (size_t)((n1 >> 3) * 32 + rowbase) * IMG
                              + (n1 & 7) * 32 + jc;
                    float* p2 = oplane + (size_t)((n2 >> 3) * 32 + rowbase) * IMG
                              + (n2 & 7) * 32 + jc;
                    *(float2*)p1 = make_float2(acc[mt][nt][0], acc[mt][nt][1]);
                    *(float2*)p2 = make_float2(acc[mt][nt][2], acc[mt][nt][3]);
                }
            }
        }
    }
}

extern "C" void kernel_launch(void* const* d_in, const int* in_sizes, int n_in,
                              void* d_out, int out_size) {
    const float* x  = (const float*)d_in[0];
    const float* Wq = (const float*)d_in[1];
    const float* Wk = (const float*)d_in[2];
    float* out = (float*)d_out;

    cudaFuncSetAttribute(att_kernel, cudaFuncAttributeMaxDynamicSharedMemorySize, SMEM_ATT);

    pool_kernel<<<NB * NC, 256>>>(x);
    dist_kernel<<<NB, 256>>>(Wq, Wk);
    att_kernel<<<NB * NC, 256, SMEM_ATT>>>(out);
}

// round 9
// speedup vs baseline: 1.0747x; 1.0747x over previous
#include <cuda_runtime.h>
#include <cuda_fp16.h>
#include <cstdint>
#include <math.h>

#define NB 16
#define NC 64
#define IMG 256
#define PLANE 65536

// scratch (device globals — no allocation allowed)
__device__ float g_y[NB * 64 * NC];                 // [b][n][c] pooled tokens
__device__ unsigned long long g_xpack[16777216];    // x fp16: [bc][ig][nh][k=64][px=128] (134MB)
__device__ __align__(16) unsigned char g_Apack[NB * 9216]; // dist fp16, 64 rows x 144B

__device__ __forceinline__ uint32_t smem_u32(const void* p) {
    uint32_t a;
    asm("{ .reg .u64 t; cvta.to.shared.u64 t, %1; cvt.u32.u64 %0, t; }"
        : "=r"(a) : "l"(p));
    return a;
}

// ---------------------------------------------------------------------------
// Kernel A: adaptive avg pool 8x8 + fp16 windowed repack of x.
// One CTA per (b,c) plane. row = mr*32 + ig*8 + il; warp = il, pass = mr*4+ig.
// Repack (u64 units): g_xpack[bc*16384 + ig*4096 + nh*2048 + k*32
//                             + (il&3)*8 + jc/4],  nh = il>>2, k = mr*8+mc.
// Each (ig,nh) tile is 16KB contiguous for streaming cp.async in att.
// ---------------------------------------------------------------------------
__global__ __launch_bounds__(256) void pool_kernel(const float* __restrict__ x) {
    int bc = blockIdx.x;
    const float* plane = x + (size_t)bc * PLANE;
    int t = threadIdx.x;
    int warp = t >> 5, lane = t & 31;

    __shared__ float wsum[64];
    if (t < 64) wsum[t] = 0.f;
    __syncthreads();

    int mc1 = lane >> 3;               // window col for first float4 (0..3)
    int jq  = lane & 7;                // jc/4 within window
    int nh  = warp >> 2;
    int il4 = warp & 3;
    unsigned long long* xp = g_xpack + (size_t)bc * 16384 + nh * 2048 + il4 * 8 + jq;

    for (int pass = 0; pass < 32; pass++) {
        int row = pass * 8 + warp;
        int mr = pass >> 2, ig = pass & 3;
        const float4* rp = (const float4*)(plane + row * IMG);
        float4 v1 = rp[lane];
        float4 v2 = rp[lane + 32];

        // fp16 repack (half4 = one u64 per float4)
        {
            __half2 a0 = __floats2half2_rn(v1.x, v1.y);
            __half2 a1 = __floats2half2_rn(v1.z, v1.w);
            __half2 b0 = __floats2half2_rn(v2.x, v2.y);
            __half2 b1 = __floats2half2_rn(v2.z, v2.w);
            unsigned long long u1 = ((unsigned long long)*(uint32_t*)&a1 << 32) | *(uint32_t*)&a0;
            unsigned long long u2 = ((unsigned long long)*(uint32_t*)&b1 << 32) | *(uint32_t*)&b0;
            xp[ig * 4096 + (mr * 8 + mc1) * 32]       = u1;
            xp[ig * 4096 + (mr * 8 + mc1 + 4) * 32]   = u2;
        }

        float s1 = v1.x + v1.y + v1.z + v1.w;
        float s2 = v2.x + v2.y + v2.z + v2.w;
        s1 += __shfl_xor_sync(~0u, s1, 4);
        s1 += __shfl_xor_sync(~0u, s1, 2);
        s1 += __shfl_xor_sync(~0u, s1, 1);
        s2 += __shfl_xor_sync(~0u, s2, 4);
        s2 += __shfl_xor_sync(~0u, s2, 2);
        s2 += __shfl_xor_sync(~0u, s2, 1);
        if ((lane & 7) == 0) {
            int wr = row >> 5;
            atomicAdd(&wsum[wr * 8 + (lane >> 3)], s1);
            atomicAdd(&wsum[wr * 8 + (lane >> 3) + 4], s2);
        }
    }
    __syncthreads();
    if (t < 64) {
        int b = bc >> 6, c = bc & 63;
        g_y[((size_t)b * 64 + t) * NC + c] = wsum[t] * (1.0f / 1024.0f);
    }
}

// ---------------------------------------------------------------------------
// Kernel B: q = yWq^T, k = yWk^T, dist = softmax(q k^T / 8). One CTA per batch.
// Output: A packed single fp16, 144B rows (the att smem image), to g_Apack.
// ---------------------------------------------------------------------------
__global__ __launch_bounds__(256) void dist_kernel(const float* __restrict__ Wq,
                                                   const float* __restrict__ Wk) {
    __shared__ float sY[4096];
    __shared__ float sA[4096];
    __shared__ float sB2[4096];
    int b = blockIdx.x, t = threadIdx.x;

    for (int idx = t; idx < 4096; idx += 256) {
        sY[idx]  = g_y[b * 4096 + idx];
        sA[idx]  = Wq[idx];
        sB2[idx] = Wk[idx];
    }
    __syncthreads();

    int n = t >> 2;
    int kk = (t & 3) * 16;

    float qv[16], kv[16];
    #pragma unroll
    for (int e = 0; e < 16; e++) {
        float aq = 0.f, ak = 0.f;
        const float* yr = &sY[n * 64];
        const float* wq = &sA[(kk + e) * 64];
        const float* wk = &sB2[(kk + e) * 64];
        #pragma unroll
        for (int c = 0; c < 64; c++) {
            aq = fmaf(yr[c], wq[c], aq);
            ak = fmaf(yr[c], wk[c], ak);
        }
        qv[e] = aq; kv[e] = ak;
    }
    __syncthreads();
    #pragma unroll
    for (int e = 0; e < 16; e++) {
        sA[n * 64 + kk + e]  = qv[e];
        sB2[n * 64 + kk + e] = kv[e];
    }
    __syncthreads();

    float sv[16];
    #pragma unroll
    for (int e = 0; e < 16; e++) {
        int m = kk + e;
        float s = 0.f;
        const float* qr = &sA[n * 64];
        const float* kr = &sB2[m * 64];
        #pragma unroll
        for (int k = 0; k < 64; k++) s = fmaf(qr[k], kr[k], s);
        sv[e] = s * 0.125f;
    }
    __syncthreads();
    #pragma unroll
    for (int e = 0; e < 16; e++) sY[n * 64 + kk + e] = sv[e];
    __syncthreads();

    // softmax + fp16 pack: lane covers col pair (2*lane, 2*lane+1)
    int warp = t >> 5, lane = t & 31;
    unsigned char* ap = g_Apack + b * 9216;
    for (int j = 0; j < 8; j++) {
        int row = warp * 8 + j;
        float2 v = *(const float2*)&sY[row * 64 + 2 * lane];
        float mx = fmaxf(v.x, v.y);
        for (int d = 16; d >= 1; d >>= 1) mx = fmaxf(mx, __shfl_xor_sync(~0u, mx, d));
        float e0 = expf(v.x - mx), e1 = expf(v.y - mx);
        float s = e0 + e1;
        for (int d = 16; d >= 1; d >>= 1) s += __shfl_xor_sync(~0u, s, d);
        float inv = 1.0f / s;
        __half2 h = __floats2half2_rn(e0 * inv, e1 * inv);
        *(uint32_t*)(ap + row * 144 + lane * 4) = *(uint32_t*)&h;
    }
}

// ---------------------------------------------------------------------------
// Kernel C (att): single-pass fp16 GEMM (legacy HMMA is ~512 MAC/cyc/SM, so
// HMMA count halved vs R8 by dropping the A-lo pass). CTA = (b,c,ig), 4096
// CTAs, 2-tile (nh) pipeline: A (9.2KB, L2-hot) + B0 async; B1 prefetched
// during tile 0. Per warp per tile: 8 B-LDSM + 8 A-LDSM + 32 HMMA + scatter.
// ---------------------------------------------------------------------------
#define SM_A  0            // 9216 B, 144B rows
#define SM_B0 9216         // 64 rows * 272B = 17408
#define SM_B1 26624
#define SMEM_ATT 44032

__global__ void __launch_bounds__(256, 3) att_kernel(float* __restrict__ out) {
    extern __shared__ char sm[];
    uint32_t sbase = smem_u32(sm);
    int t = threadIdx.x;
    int wid = t >> 5, lane = t & 31;
    int wm = wid >> 2, wn = wid & 3;

    int blk = blockIdx.x;
    int ig = blk & 3;
    int c  = (blk >> 2) & 63;
    int b  = blk >> 8;

    const char* gB = (const char*)g_xpack + (size_t)blk * 32768;  // blk == (b*64+c)*4+ig

    // ---- group 0: A image + B tile 0 ----
    {
        const char* gA = (const char*)g_Apack + b * 9216;
        #pragma unroll
        for (int idx = t; idx < 576; idx += 256) {
            uint32_t d = sbase + SM_A + idx * 16;
            asm volatile("cp.async.cg.shared.global [%0], [%1], 16;"
                         :: "r"(d), "l"(gA + idx * 16));
        }
        #pragma unroll
        for (int idx = t; idx < 1024; idx += 256) {
            int row = idx >> 4, ch = idx & 15;
            uint32_t d = sbase + SM_B0 + row * 272 + ch * 16;
            asm volatile("cp.async.cg.shared.global [%0], [%1], 16;"
                         :: "r"(d), "l"(gB + row * 256 + ch * 16));
        }
        asm volatile("cp.async.commit_group;");
    }

    int row16 = lane & 15;
    uint32_t aH = sbase + SM_A + (uint32_t)(wm * 32 + row16) * 144u + (uint32_t)(lane >> 4) * 16u;
    uint32_t bLane = (uint32_t)row16 * 272u + (uint32_t)(wn * 64);
    float* oplane = out + (size_t)(b * 64 + c) * PLANE;

    uint32_t bufOff[2] = { sbase + SM_B0, sbase + SM_B1 };

    #pragma unroll
    for (int i = 0; i < 2; i++) {
        if (i == 0) {
            // prefetch B tile 1
            const char* src = gB + 16384;
            #pragma unroll
            for (int idx = t; idx < 1024; idx += 256) {
                int row = idx >> 4, ch = idx & 15;
                asm volatile("cp.async.cg.shared.global [%0], [%1], 16;"
                             :: "r"(sbase + SM_B1 + row * 272 + ch * 16),
                                "l"(src + row * 256 + ch * 16));
            }
            asm volatile("cp.async.commit_group;");
            asm volatile("cp.async.wait_group 1;" ::: "memory");
        } else {
            asm volatile("cp.async.wait_group 0;" ::: "memory");
        }
        __syncthreads();

        // ---- MMA on buf i ----
        float acc[2][4][4];
        #pragma unroll
        for (int mt = 0; mt < 2; mt++)
            #pragma unroll
            for (int nt = 0; nt < 4; nt++) {
                acc[mt][nt][0] = 0.f; acc[mt][nt][1] = 0.f;
                acc[mt][nt][2] = 0.f; acc[mt][nt][3] = 0.f;
            }
        uint32_t bB = bufOff[i] + bLane;

        #pragma unroll
        for (int kk = 0; kk < 4; kk++) {
            uint32_t bh[4][2];
            #pragma unroll
            for (int nt = 0; nt < 4; nt++) {
                uint32_t addr = bB + (uint32_t)(kk * 16) * 272u + (uint32_t)(nt * 16);
                asm volatile("ldmatrix.sync.aligned.m8n8.x2.trans.shared.b16 {%0,%1}, [%2];"
                             : "=r"(bh[nt][0]), "=r"(bh[nt][1]) : "r"(addr));
            }
            #pragma unroll
            for (int mt = 0; mt < 2; mt++) {
                uint32_t af[4];
                uint32_t addr = aH + (uint32_t)(mt * 16) * 144u + (uint32_t)(kk * 32);
                asm volatile("ldmatrix.sync.aligned.m8n8.x4.shared.b16 {%0,%1,%2,%3}, [%4];"
                             : "=r"(af[0]), "=r"(af[1]), "=r"(af[2]), "=r"(af[3]) : "r"(addr));
                #pragma unroll
                for (int nt = 0; nt < 4; nt++)
                    asm volatile(
                        "mma.sync.aligned.m16n8k16.row.col.f32.f16.f16.f32 "
                        "{%0,%1,%2,%3}, {%4,%5,%6,%7}, {%8,%9}, {%0,%1,%2,%3};"
                        : "+f"(acc[mt][nt][0]), "+f"(acc[mt][nt][1]),
                          "+f"(acc[mt][nt][2]), "+f"(acc[mt][nt][3])
                        : "r"(af[0]), "r"(af[1]), "r"(af[2]), "r"(af[3]),
                          "r"(bh[nt][0]), "r"(bh[nt][1]));
            }
        }

        // ---- epilogue: direct scatter (fully-used 32B sectors) ----
        {
            int g = lane >> 2, tig = lane & 3;
            int rowbase = ig * 8 + i * 4 + wn;     // il = nh*4 + wn
            #pragma unroll
            for (int mt = 0; mt < 2; mt++) {
                #pragma unroll
                for (int nt = 0; nt < 4; nt++) {
                    int jc = nt * 8 + tig * 2;
                    int n1 = wm * 32 + mt * 16 + g;
                    int n2 = n1 + 8;
                    float* p1 = oplane + (size_t)((n1 >> 3) * 32 + rowbase) * IMG
                              + (n1 & 7) * 32 + jc;
                    float* p2 = oplane + (size_t)((n2 >> 3) * 32 + rowbase) * IMG
                              + (n2 & 7) * 32 + jc;
                    *(float2*)p1 = make_float2(acc[mt][nt][0], acc[mt][nt][1]);
                    *(float2*)p2 = make_float2(acc[mt][nt][2], acc[mt][nt][3]);
                }
            }
        }
    }
}

extern "C" void kernel_launch(void* const* d_in, const int* in_sizes, int n_in,
                              void* d_out, int out_size) {
    const float* x  = (const float*)d_in[0];
    const float* Wq = (const float*)d_in[1];
    const float* Wk = (const float*)d_in[2];
    float* out = (float*)d_out;

    cudaFuncSetAttribute(att_kernel, cudaFuncAttributeMaxDynamicSharedMemorySize, SMEM_ATT);

    pool_kernel<<<NB * NC, 256>>>(x);
    dist_kernel<<<NB, 256>>>(Wq, Wk);
    att_kernel<<<NB * NC * 4, 256, SMEM_ATT>>>(out);
}